// round 1
// baseline (speedup 1.0000x reference)
#include <cuda_runtime.h>
#include <cstdint>

#define N_USERS 100000
#define N_ITEMS 50000
#define N_NODES 150000
#define N_REL   5
#define NNZ     2000000
#define TOTE    (N_REL * NNZ)
#define D       64
#define B_EVAL  16384
#define NROWS   (2 * B_EVAL)
#define MASK_BYTES 150016

// Scratch (device globals; no allocations allowed)
__device__ float g_agg[(size_t)N_REL * N_NODES * D];   // 192 MB, only needed rows touched
__device__ unsigned char g_mask[MASK_BYTES];
__device__ float g_logits[(size_t)NROWS * D];

// ---------------------------------------------------------------------------
// K0: clear node mask
__global__ void clear_mask_kernel() {
    int i = blockIdx.x * blockDim.x + threadIdx.x;
    if (i < MASK_BYTES / 4) reinterpret_cast<int*>(g_mask)[i] = 0;
}

// ---------------------------------------------------------------------------
// K1: set mask for needed nodes + zero their agg rows (warp per batch row)
__global__ void prep_kernel(const int* __restrict__ users, const int* __restrict__ items) {
    int w = (blockIdx.x * blockDim.x + threadIdx.x) >> 5;
    int lane = threadIdx.x & 31;
    if (w >= NROWS) return;
    int node = (w < B_EVAL) ? users[w] : (N_USERS + items[w - B_EVAL]);
    if (lane == 0) g_mask[node] = 1;
#pragma unroll
    for (int k = 0; k < N_REL; k++) {
        float2* row = reinterpret_cast<float2*>(g_agg + ((size_t)k * N_NODES + node) * D);
        row[lane] = make_float2(0.f, 0.f);
    }
}

// ---------------------------------------------------------------------------
// K2: masked edge scatter. Warp scans 32 coalesced edges, ballots survivors,
// processes 2 survivors per iteration (half-warp each): 256B coalesced E-row
// gather + red.global.add.v4.f32 into the agg row.
__global__ void __launch_bounds__(256) scatter_kernel(
    const int* __restrict__ rows, const int* __restrict__ cols,
    const float* __restrict__ vals,
    const float* __restrict__ uemb, const float* __restrict__ iemb)
{
    int e = blockIdx.x * blockDim.x + threadIdx.x;
    int lane = threadIdx.x & 31;
    bool valid = (e < TOTE);
    int r = 0, c = 0;
    float v = 0.f;
    if (valid) r = rows[e];
    bool p = valid && (g_mask[r] != 0);
    if (p) { c = cols[e]; v = vals[e]; }
    unsigned bal = __ballot_sync(0xFFFFFFFFu, p);
    int k = valid ? (e / NNZ) : 0;   // warp-uniform (NNZ % 32 == 0, TOTE % 32 == 0)
    int half = lane >> 4;
    int sub  = lane & 15;
    while (bal) {
        int l0 = __ffs(bal) - 1; bal &= bal - 1;
        int l1 = 32;
        if (bal) { l1 = __ffs(bal) - 1; bal &= bal - 1; }
        int src = half ? l1 : l0;
        int s2  = (src == 32) ? l0 : src;
        int   rr = __shfl_sync(0xFFFFFFFFu, r, s2);
        int   cc = __shfl_sync(0xFFFFFFFFu, c, s2);
        float vv = __shfl_sync(0xFFFFFFFFu, v, s2);
        if (src != 32) {
            const float* Erow = (cc < N_USERS)
                ? (uemb + (size_t)cc * D)
                : (iemb + (size_t)(cc - N_USERS) * D);
            float4 x = reinterpret_cast<const float4*>(Erow)[sub];
            float* dst = g_agg + ((size_t)k * N_NODES + rr) * D + sub * 4;
            asm volatile("red.global.add.v4.f32 [%0], {%1, %2, %3, %4};"
                         :: "l"(dst), "f"(x.x * vv), "f"(x.y * vv),
                            "f"(x.z * vv), "f"(x.w * vv)
                         : "memory");
        }
    }
}

// ---------------------------------------------------------------------------
// K3: fused dense chain per 128-row tile:
//   for k: Y = leaky(X_k @ W_k + b_k);  acc2 += Y @ A_k
//   logits = acc2 + affine_b
// 256 threads, 8x4 register tiles; sX reused for Y, sW reused for A_k.
__global__ void __launch_bounds__(256) gemm_kernel(
    const int* __restrict__ users, const int* __restrict__ items,
    const float* __restrict__ W_rel, const float* __restrict__ b_rel,
    const float* __restrict__ affine_W, const float* __restrict__ affine_b)
{
    __shared__ float sX[128 * 64];   // X tile, then Y tile
    __shared__ float sW[64 * 64];    // W_k, then A_k

    int t  = threadIdx.x;
    int tx = t & 15;        // 16 col groups * 4 cols
    int ty = t >> 4;        // 16 row groups * 8 rows
    int rowBase = blockIdx.x * 128;

    float acc2[8][4];
#pragma unroll
    for (int i = 0; i < 8; i++)
#pragma unroll
        for (int j = 0; j < 4; j++) acc2[i][j] = 0.f;

    for (int k = 0; k < N_REL; k++) {
        __syncthreads();
        // load X tile (2 threads per row, 128B each)
        {
            int r = t >> 1, part = t & 1;
            int brow = rowBase + r;
            int node = (brow < B_EVAL) ? users[brow] : (N_USERS + items[brow - B_EVAL]);
            const float4* src = reinterpret_cast<const float4*>(
                g_agg + ((size_t)k * N_NODES + node) * D + part * 32);
            float4* dst = reinterpret_cast<float4*>(&sX[r * 64 + part * 32]);
#pragma unroll
            for (int m = 0; m < 8; m++) dst[m] = src[m];
        }
        // load W_k
        {
            const float4* src = reinterpret_cast<const float4*>(W_rel + (size_t)k * 64 * 64);
            float4* dst = reinterpret_cast<float4*>(sW);
            for (int m = t; m < 1024; m += 256) dst[m] = src[m];
        }
        __syncthreads();

        // GEMM1: acc1 = bias; acc1 += X @ W
        float acc1[8][4];
#pragma unroll
        for (int j = 0; j < 4; j++) {
            float bb = b_rel[k * 64 + tx * 4 + j];
#pragma unroll
            for (int i = 0; i < 8; i++) acc1[i][j] = bb;
        }
        for (int kk = 0; kk < 64; kk++) {
            float a[8];
#pragma unroll
            for (int i = 0; i < 8; i++) a[i] = sX[(ty * 8 + i) * 64 + kk];
            float4 bb = *reinterpret_cast<const float4*>(&sW[kk * 64 + tx * 4]);
#pragma unroll
            for (int i = 0; i < 8; i++) {
                acc1[i][0] += a[i] * bb.x;
                acc1[i][1] += a[i] * bb.y;
                acc1[i][2] += a[i] * bb.z;
                acc1[i][3] += a[i] * bb.w;
            }
        }
        __syncthreads();   // everyone done reading sX / sW

        // leaky + write Y into sX; load A_k into sW
#pragma unroll
        for (int i = 0; i < 8; i++)
#pragma unroll
            for (int j = 0; j < 4; j++) {
                float y = acc1[i][j];
                y = (y > 0.f) ? y : 0.2f * y;
                sX[(ty * 8 + i) * 64 + tx * 4 + j] = y;
            }
        {
            const float4* src = reinterpret_cast<const float4*>(affine_W + (size_t)k * 64 * 64);
            float4* dst = reinterpret_cast<float4*>(sW);
            for (int m = t; m < 1024; m += 256) dst[m] = src[m];
        }
        __syncthreads();

        // GEMM2: acc2 += Y @ A_k
        for (int kk = 0; kk < 64; kk++) {
            float a[8];
#pragma unroll
            for (int i = 0; i < 8; i++) a[i] = sX[(ty * 8 + i) * 64 + kk];
            float4 bb = *reinterpret_cast<const float4*>(&sW[kk * 64 + tx * 4]);
#pragma unroll
            for (int i = 0; i < 8; i++) {
                acc2[i][0] += a[i] * bb.x;
                acc2[i][1] += a[i] * bb.y;
                acc2[i][2] += a[i] * bb.z;
                acc2[i][3] += a[i] * bb.w;
            }
        }
    }

    // epilogue: + affine_b, store logits
    float ab[4];
#pragma unroll
    for (int j = 0; j < 4; j++) ab[j] = affine_b[tx * 4 + j];
#pragma unroll
    for (int i = 0; i < 8; i++) {
        int row = rowBase + ty * 8 + i;
#pragma unroll
        for (int j = 0; j < 4; j++)
            g_logits[(size_t)row * D + tx * 4 + j] = acc2[i][j] + ab[j];
    }
}

// ---------------------------------------------------------------------------
// K4: out[b] = dot(logits[b], logits[B_EVAL + b])
__global__ void dot_kernel(float* __restrict__ out) {
    int b = blockIdx.x * blockDim.x + threadIdx.x;
    if (b >= B_EVAL) return;
    const float4* u = reinterpret_cast<const float4*>(g_logits + (size_t)b * D);
    const float4* v = reinterpret_cast<const float4*>(g_logits + (size_t)(B_EVAL + b) * D);
    float s = 0.f;
#pragma unroll
    for (int m = 0; m < 16; m++) {
        float4 a = u[m], c = v[m];
        s += a.x * c.x + a.y * c.y + a.z * c.z + a.w * c.w;
    }
    out[b] = s;
}

// ---------------------------------------------------------------------------
extern "C" void kernel_launch(void* const* d_in, const int* in_sizes, int n_in,
                              void* d_out, int out_size) {
    const int*   users    = (const int*)  d_in[0];
    const int*   items    = (const int*)  d_in[1];
    const int*   rows     = (const int*)  d_in[2];
    const int*   cols     = (const int*)  d_in[3];
    const float* vals     = (const float*)d_in[4];
    const float* uemb     = (const float*)d_in[5];
    const float* iemb     = (const float*)d_in[6];
    const float* W_rel    = (const float*)d_in[7];
    const float* b_rel    = (const float*)d_in[8];
    const float* affine_W = (const float*)d_in[9];
    const float* affine_b = (const float*)d_in[10];
    float* out = (float*)d_out;

    clear_mask_kernel<<<(MASK_BYTES / 4 + 255) / 256, 256>>>();
    prep_kernel<<<(NROWS * 32 + 255) / 256, 256>>>(users, items);
    scatter_kernel<<<(TOTE + 255) / 256, 256>>>(rows, cols, vals, uemb, iemb);
    gemm_kernel<<<NROWS / 128, 256>>>(users, items, W_rel, b_rel, affine_W, affine_b);
    dot_kernel<<<(B_EVAL + 255) / 256, 256>>>(out);
}